// round 5
// baseline (speedup 1.0000x reference)
#include <cuda_runtime.h>
#include <cuda_bf16.h>
#include <math.h>
#include <stdint.h>

// Problem constants (fixed by reference setup_inputs)
#define BATCH 2
#define SEQ   2048
#define DIM   1024
#define HEADS 16
#define DHEAD 64
#define MROWS (BATCH * SEQ)   // 4096

// -------- device scratch ----------------------------------------------------
__device__ float g_q[MROWS * DIM];
__device__ float g_k[MROWS * DIM];
__device__ float g_v[MROWS * DIM];
__device__ float g_attn[MROWS * DIM];

__device__ __forceinline__ uint32_t f2tf32(float f) {
    uint32_t r;
    asm("cvt.rna.tf32.f32 %0, %1;" : "=r"(r) : "f"(f));
    return r;
}
__device__ __forceinline__ uint32_t raw2tf32(uint32_t raw) {
    return f2tf32(__uint_as_float(raw));
}

__device__ __forceinline__ void mma_tf32(float c[4], const uint32_t a[4],
                                         const uint32_t b[2]) {
    asm volatile(
        "mma.sync.aligned.m16n8k8.row.col.f32.tf32.tf32.f32 "
        "{%0,%1,%2,%3}, {%4,%5,%6,%7}, {%8,%9}, {%0,%1,%2,%3};\n"
        : "+f"(c[0]), "+f"(c[1]), "+f"(c[2]), "+f"(c[3])
        : "r"(a[0]), "r"(a[1]), "r"(a[2]), "r"(a[3]),
          "r"(b[0]), "r"(b[1]));
}

#define CP_ASYNC16(dst_u32, src_ptr) \
    asm volatile("cp.async.cg.shared.global [%0], [%1], 16;\n" \
                 :: "r"(dst_u32), "l"(src_ptr) : "memory")
#define CP_COMMIT() asm volatile("cp.async.commit_group;\n" ::: "memory")
#define CP_WAIT0()  asm volatile("cp.async.wait_group 0;\n" ::: "memory")
#define CP_WAIT1()  asm volatile("cp.async.wait_group 1;\n" ::: "memory")

__device__ __forceinline__ uint32_t smem_u32(const void* p) {
    uint32_t a;
    asm("{ .reg .u64 t; cvta.to.shared.u64 t, %1; cvt.u32.u64 %0, t; }"
        : "=r"(a) : "l"(p));
    return a;
}

// ============================================================================
// TF32 tensor-core GEMM: C[M,N] = scale * (A[M,K] @ B[N,K]^T) + bias[N]
// (unchanged from R2 — validated at ~70us per 4096x1024x1024)
// ============================================================================
#define GBM 128
#define GBN 128
#define GBK 32
#define GSTRIDE 36

__global__ __launch_bounds__(256)
void gemm_tf32(const float* __restrict__ A, const float* __restrict__ B,
               float* __restrict__ C, int M, int N, int K,
               float scale, const float* __restrict__ bias)
{
    __shared__ uint32_t As[GBM * GSTRIDE];
    __shared__ uint32_t Bs[GBN * GSTRIDE];

    const int tid  = threadIdx.x;
    const int lane = tid & 31;
    const int warp = tid >> 5;
    const int warp_m = warp >> 1;
    const int warp_n = warp & 1;
    const int row0 = blockIdx.y * GBM;
    const int col0 = blockIdx.x * GBN;

    const int ldr = tid >> 3;
    const int ldc = (tid & 7) << 2;

    float acc[2][8][4];
#pragma unroll
    for (int i = 0; i < 2; i++)
#pragma unroll
        for (int j = 0; j < 8; j++)
#pragma unroll
            for (int c = 0; c < 4; c++) acc[i][j][c] = 0.f;

    float4 pa[4], pb[4];

#pragma unroll
    for (int i = 0; i < 4; i++) {
        pa[i] = *(const float4*)(A + (size_t)(row0 + ldr + 32 * i) * K + ldc);
        pb[i] = *(const float4*)(B + (size_t)(col0 + ldr + 32 * i) * K + ldc);
    }
#pragma unroll
    for (int i = 0; i < 4; i++) {
        const int r = ldr + 32 * i;
        As[r * GSTRIDE + ldc + 0] = f2tf32(pa[i].x);
        As[r * GSTRIDE + ldc + 1] = f2tf32(pa[i].y);
        As[r * GSTRIDE + ldc + 2] = f2tf32(pa[i].z);
        As[r * GSTRIDE + ldc + 3] = f2tf32(pa[i].w);
        Bs[r * GSTRIDE + ldc + 0] = f2tf32(pb[i].x);
        Bs[r * GSTRIDE + ldc + 1] = f2tf32(pb[i].y);
        Bs[r * GSTRIDE + ldc + 2] = f2tf32(pb[i].z);
        Bs[r * GSTRIDE + ldc + 3] = f2tf32(pb[i].w);
    }
    __syncthreads();

    for (int k0 = 0; k0 < K; k0 += GBK) {
        const bool has_next = (k0 + GBK) < K;
        if (has_next) {
#pragma unroll
            for (int i = 0; i < 4; i++) {
                pa[i] = *(const float4*)(A + (size_t)(row0 + ldr + 32 * i) * K + k0 + GBK + ldc);
                pb[i] = *(const float4*)(B + (size_t)(col0 + ldr + 32 * i) * K + k0 + GBK + ldc);
            }
        }

#pragma unroll
        for (int ks = 0; ks < 4; ks++) {
            const int kk = ks * 8 + (lane & 3);
            uint32_t afrag[2][4];
#pragma unroll
            for (int tm = 0; tm < 2; tm++) {
                const int r = warp_m * 32 + tm * 16 + (lane >> 2);
                afrag[tm][0] = As[r * GSTRIDE + kk];
                afrag[tm][1] = As[(r + 8) * GSTRIDE + kk];
                afrag[tm][2] = As[r * GSTRIDE + kk + 4];
                afrag[tm][3] = As[(r + 8) * GSTRIDE + kk + 4];
            }
            uint32_t bfrag[8][2];
#pragma unroll
            for (int tn = 0; tn < 8; tn++) {
                const int n = warp_n * 64 + tn * 8 + (lane >> 2);
                bfrag[tn][0] = Bs[n * GSTRIDE + kk];
                bfrag[tn][1] = Bs[n * GSTRIDE + kk + 4];
            }
#pragma unroll
            for (int tm = 0; tm < 2; tm++)
#pragma unroll
                for (int tn = 0; tn < 8; tn++)
                    mma_tf32(acc[tm][tn], afrag[tm], bfrag[tn]);
        }

        if (has_next) {
            __syncthreads();
#pragma unroll
            for (int i = 0; i < 4; i++) {
                const int r = ldr + 32 * i;
                As[r * GSTRIDE + ldc + 0] = f2tf32(pa[i].x);
                As[r * GSTRIDE + ldc + 1] = f2tf32(pa[i].y);
                As[r * GSTRIDE + ldc + 2] = f2tf32(pa[i].z);
                As[r * GSTRIDE + ldc + 3] = f2tf32(pa[i].w);
                Bs[r * GSTRIDE + ldc + 0] = f2tf32(pb[i].x);
                Bs[r * GSTRIDE + ldc + 1] = f2tf32(pb[i].y);
                Bs[r * GSTRIDE + ldc + 2] = f2tf32(pb[i].z);
                Bs[r * GSTRIDE + ldc + 3] = f2tf32(pb[i].w);
            }
            __syncthreads();
        }
    }

#pragma unroll
    for (int tm = 0; tm < 2; tm++) {
#pragma unroll
        for (int tn = 0; tn < 8; tn++) {
            const int r = row0 + warp_m * 32 + tm * 16 + (lane >> 2);
            const int c = col0 + warp_n * 64 + tn * 8 + ((lane & 3) << 1);
            const float b0 = bias ? bias[c]     : 0.f;
            const float b1 = bias ? bias[c + 1] : 0.f;
            float2 v0, v1;
            v0.x = acc[tm][tn][0] * scale + b0;
            v0.y = acc[tm][tn][1] * scale + b1;
            v1.x = acc[tm][tn][2] * scale + b0;
            v1.y = acc[tm][tn][3] * scale + b1;
            *(float2*)(C + (size_t)r * N + c)       = v0;
            *(float2*)(C + (size_t)(r + 8) * N + c) = v1;
        }
    }
}

// ============================================================================
// TF32 tensor-core flash attention, cp.async pipelined.
// Block = 64 query rows of one (b,h). 128 threads = 4 warps, 16 rows/warp.
// Smem (all stride 72, 4 buffers of 64x72 words = 72KB total -> 3 CTAs/SM):
//   Kbuf[0], Kbuf[1] : raw fp32 K tiles (double buffer, cross-iter prefetch)
//   Vbuf             : raw fp32 V tile (prefetched at iter top, used after S)
//   QPbuf            : Q (tf32) then reused as P (tf32)
// K/V converted to tf32 at fragment-load time (cvt.rna — numerics identical
// to converting at staging).
// ============================================================================
#define FST 72
#define FTILE (64 * FST)                  // words per buffer
#define FA_SMEM (4 * FTILE * 4)           // 73728 bytes

__global__ __launch_bounds__(128)
void flash_attn_tc(const float* __restrict__ Q, const float* __restrict__ K,
                   const float* __restrict__ V, float* __restrict__ O)
{
    extern __shared__ uint32_t usm[];
    uint32_t* Kb0 = usm;
    uint32_t* Kb1 = usm + FTILE;
    uint32_t* Vs  = usm + 2 * FTILE;
    uint32_t* QP  = usm + 3 * FTILE;      // Q tile, then P tile

    const int b  = blockIdx.z;
    const int h  = blockIdx.y;
    const int q0 = blockIdx.x * 64;

    const float* Qg = Q + (size_t)b * SEQ * DIM + h * DHEAD;
    const float* Kg = K + (size_t)b * SEQ * DIM + h * DHEAD;
    const float* Vg = V + (size_t)b * SEQ * DIM + h * DHEAD;
    float*       Og = O + (size_t)b * SEQ * DIM + h * DHEAD;

    const int tid  = threadIdx.x;
    const int lane = tid & 31;
    const int warp = tid >> 5;          // 0..3 -> 16-row band
    const int g = lane >> 2;            // 0..7
    const int t = lane & 3;             // 0..3
    const int wrow = warp * 16;

    // staging coords: 8 chunks of float4 per thread per tile
    const int sr = tid >> 4;            // 0..7  (row base, +8 per chunk)
    const int sc = (tid & 15) << 2;     // 0,4,...,60

    const uint32_t k0_u32 = smem_u32(Kb0);
    const uint32_t k1_u32 = smem_u32(Kb1);
    const uint32_t v_u32  = smem_u32(Vs);

    // ---- load Q tile -> QP (tf32, register path) ----
#pragma unroll
    for (int it = 0; it < 8; it++) {
        const int r = sr + it * 8;
        float4 v4 = *(const float4*)(Qg + (size_t)(q0 + r) * DIM + sc);
        QP[r * FST + sc + 0] = f2tf32(v4.x);
        QP[r * FST + sc + 1] = f2tf32(v4.y);
        QP[r * FST + sc + 2] = f2tf32(v4.z);
        QP[r * FST + sc + 3] = f2tf32(v4.w);
    }

    // ---- prefetch K tile 0 into Kb0 ----
#pragma unroll
    for (int it = 0; it < 8; it++) {
        const int r = sr + it * 8;
        CP_ASYNC16(k0_u32 + (r * FST + sc) * 4, Kg + (size_t)r * DIM + sc);
    }
    CP_COMMIT();

    __syncthreads();

    // ---- hoist Q fragments ----
    uint32_t qf[8][4];
#pragma unroll
    for (int ks = 0; ks < 8; ks++) {
        const int kk = ks * 8 + t;
        qf[ks][0] = QP[(wrow + g) * FST + kk];
        qf[ks][1] = QP[(wrow + g + 8) * FST + kk];
        qf[ks][2] = QP[(wrow + g) * FST + kk + 4];
        qf[ks][3] = QP[(wrow + g + 8) * FST + kk + 4];
    }
    __syncthreads();   // QP free to become P

    float oacc[8][4];
#pragma unroll
    for (int j = 0; j < 8; j++)
#pragma unroll
        for (int c = 0; c < 4; c++) oacc[j][c] = 0.f;
    float m_lo = -INFINITY, m_hi = -INFINITY;
    float l_lo = 0.f, l_hi = 0.f;

    const int NT = SEQ / 64;   // 32
    for (int ti = 0; ti < NT; ti++) {
        const uint32_t* Kcur = (ti & 1) ? Kb1 : Kb0;
        const uint32_t  knext_u32 = (ti & 1) ? k0_u32 : k1_u32;

        CP_WAIT0();            // K(ti) landed
        __syncthreads();       // K visible to all; V/K-other buffers free

        // prefetch V(ti) (group A), then K(ti+1) (group B)
#pragma unroll
        for (int it = 0; it < 8; it++) {
            const int r = sr + it * 8;
            CP_ASYNC16(v_u32 + (r * FST + sc) * 4,
                       Vg + (size_t)(ti * 64 + r) * DIM + sc);
        }
        CP_COMMIT();
        if (ti + 1 < NT) {
#pragma unroll
            for (int it = 0; it < 8; it++) {
                const int r = sr + it * 8;
                CP_ASYNC16(knext_u32 + (r * FST + sc) * 4,
                           Kg + (size_t)((ti + 1) * 64 + r) * DIM + sc);
            }
        }
        CP_COMMIT();           // always commit (empty group OK on last iter)

        // ---- S = Q @ K^T ----
        float sacc[8][4];
#pragma unroll
        for (int j = 0; j < 8; j++)
#pragma unroll
            for (int c = 0; c < 4; c++) sacc[j][c] = 0.f;

#pragma unroll
        for (int ks = 0; ks < 8; ks++) {
            const int kk = ks * 8 + t;
            uint32_t bf[8][2];
#pragma unroll
            for (int j = 0; j < 8; j++) {
                bf[j][0] = raw2tf32(Kcur[(j * 8 + g) * FST + kk]);
                bf[j][1] = raw2tf32(Kcur[(j * 8 + g) * FST + kk + 4]);
            }
#pragma unroll
            for (int j = 0; j < 8; j++)
                mma_tf32(sacc[j], qf[ks], bf[j]);
        }

        // ---- online softmax ----
        float mx_lo = -INFINITY, mx_hi = -INFINITY;
#pragma unroll
        for (int j = 0; j < 8; j++) {
            mx_lo = fmaxf(mx_lo, fmaxf(sacc[j][0], sacc[j][1]));
            mx_hi = fmaxf(mx_hi, fmaxf(sacc[j][2], sacc[j][3]));
        }
        mx_lo = fmaxf(mx_lo, __shfl_xor_sync(0xffffffffu, mx_lo, 1));
        mx_lo = fmaxf(mx_lo, __shfl_xor_sync(0xffffffffu, mx_lo, 2));
        mx_hi = fmaxf(mx_hi, __shfl_xor_sync(0xffffffffu, mx_hi, 1));
        mx_hi = fmaxf(mx_hi, __shfl_xor_sync(0xffffffffu, mx_hi, 2));

        const float mnew_lo = fmaxf(m_lo, mx_lo);
        const float mnew_hi = fmaxf(m_hi, mx_hi);
        const float corr_lo = __expf(m_lo - mnew_lo);
        const float corr_hi = __expf(m_hi - mnew_hi);
        m_lo = mnew_lo; m_hi = mnew_hi;

        float sum_lo = 0.f, sum_hi = 0.f;
#pragma unroll
        for (int j = 0; j < 8; j++) {
            const float p0 = __expf(sacc[j][0] - mnew_lo);
            const float p1 = __expf(sacc[j][1] - mnew_lo);
            const float p2 = __expf(sacc[j][2] - mnew_hi);
            const float p3 = __expf(sacc[j][3] - mnew_hi);
            sum_lo += p0 + p1;
            sum_hi += p2 + p3;
            uint2 plo, phi;
            plo.x = f2tf32(p0); plo.y = f2tf32(p1);
            phi.x = f2tf32(p2); phi.y = f2tf32(p3);
            *(uint2*)(QP + (wrow + g) * FST + j * 8 + 2 * t)     = plo;
            *(uint2*)(QP + (wrow + g + 8) * FST + j * 8 + 2 * t) = phi;
        }
        sum_lo += __shfl_xor_sync(0xffffffffu, sum_lo, 1);
        sum_lo += __shfl_xor_sync(0xffffffffu, sum_lo, 2);
        sum_hi += __shfl_xor_sync(0xffffffffu, sum_hi, 1);
        sum_hi += __shfl_xor_sync(0xffffffffu, sum_hi, 2);
        l_lo = l_lo * corr_lo + sum_lo;
        l_hi = l_hi * corr_hi + sum_hi;

#pragma unroll
        for (int j = 0; j < 8; j++) {
            oacc[j][0] *= corr_lo; oacc[j][1] *= corr_lo;
            oacc[j][2] *= corr_hi; oacc[j][3] *= corr_hi;
        }

        CP_WAIT1();            // V(ti) landed (K(ti+1) may still be in flight)
        __syncthreads();       // V visible; P rows are warp-private (hoisted qf)
        __syncwarp();

        // ---- O += P @ V ----
#pragma unroll
        for (int ks = 0; ks < 8; ks++) {
            const int kk = ks * 8 + t;
            uint32_t af[4];
            af[0] = QP[(wrow + g) * FST + kk];
            af[1] = QP[(wrow + g + 8) * FST + kk];
            af[2] = QP[(wrow + g) * FST + kk + 4];
            af[3] = QP[(wrow + g + 8) * FST + kk + 4];
            uint32_t bf[8][2];
#pragma unroll
            for (int j = 0; j < 8; j++) {
                bf[j][0] = raw2tf32(Vs[(ks * 8 + t) * FST + j * 8 + g]);
                bf[j][1] = raw2tf32(Vs[(ks * 8 + t + 4) * FST + j * 8 + g]);
            }
#pragma unroll
            for (int j = 0; j < 8; j++)
                mma_tf32(oacc[j], af, bf[j]);
        }
    }

    // ---- epilogue ----
    const float inv_lo = 1.f / l_lo;
    const float inv_hi = 1.f / l_hi;
    const int r_lo = q0 + wrow + g;
    const int r_hi = r_lo + 8;
#pragma unroll
    for (int j = 0; j < 8; j++) {
        const int c = j * 8 + 2 * t;
        float2 vlo, vhi;
        vlo.x = oacc[j][0] * inv_lo; vlo.y = oacc[j][1] * inv_lo;
        vhi.x = oacc[j][2] * inv_hi; vhi.y = oacc[j][3] * inv_hi;
        *(float2*)(Og + (size_t)r_lo * DIM + c) = vlo;
        *(float2*)(Og + (size_t)r_hi * DIM + c) = vhi;
    }
}

// ============================================================================
// kernel_launch
// ============================================================================
extern "C" void kernel_launch(void* const* d_in, const int* in_sizes, int n_in,
                              void* d_out, int out_size)
{
    const float* x   = (const float*)d_in[0];
    const float* Wq  = (const float*)d_in[1];
    const float* Wk  = (const float*)d_in[2];
    const float* Wv  = (const float*)d_in[3];
    const float* Wff = (const float*)d_in[4];
    const float* bff = (const float*)d_in[5];
    float* out = (float*)d_out;

    float *q, *k, *v, *attn;
    cudaGetSymbolAddress((void**)&q,    g_q);
    cudaGetSymbolAddress((void**)&k,    g_k);
    cudaGetSymbolAddress((void**)&v,    g_v);
    cudaGetSymbolAddress((void**)&attn, g_attn);

    cudaFuncSetAttribute(flash_attn_tc,
                         cudaFuncAttributeMaxDynamicSharedMemorySize, FA_SMEM);

    dim3 gemm_grid(DIM / GBN, MROWS / GBM);   // (8, 32)
    const float qscale = 1.0f / 32.0f;        // 1/sqrt(1024)

    gemm_tf32<<<gemm_grid, 256>>>(x, Wq, q, MROWS, DIM, DIM, qscale, nullptr);
    gemm_tf32<<<gemm_grid, 256>>>(x, Wk, k, MROWS, DIM, DIM, 1.0f, nullptr);
    gemm_tf32<<<gemm_grid, 256>>>(x, Wv, v, MROWS, DIM, DIM, 1.0f, nullptr);

    dim3 att_grid(SEQ / 64, HEADS, BATCH);    // (32, 16, 2)
    flash_attn_tc<<<att_grid, 128, FA_SMEM>>>(q, k, v, attn);

    gemm_tf32<<<gemm_grid, 256>>>(attn, Wff, out, MROWS, DIM, DIM, 1.0f, bff);
}

// round 7
// speedup vs baseline: 1.1122x; 1.1122x over previous
#include <cuda_runtime.h>
#include <cuda_bf16.h>
#include <math.h>
#include <stdint.h>

// Problem constants (fixed by reference setup_inputs)
#define BATCH 2
#define SEQ   2048
#define DIM   1024
#define HEADS 16
#define DHEAD 64
#define MROWS (BATCH * SEQ)   // 4096

// -------- device scratch ----------------------------------------------------
__device__ float g_q[MROWS * DIM];
__device__ float g_k[MROWS * DIM];
__device__ float g_v[MROWS * DIM];
__device__ float g_attn[MROWS * DIM];

__device__ __forceinline__ uint32_t f2tf32(float f) {
    uint32_t r;
    asm("cvt.rna.tf32.f32 %0, %1;" : "=r"(r) : "f"(f));
    return r;
}

__device__ __forceinline__ void mma_tf32(float c[4], const uint32_t a[4],
                                         const uint32_t b[2]) {
    asm volatile(
        "mma.sync.aligned.m16n8k8.row.col.f32.tf32.tf32.f32 "
        "{%0,%1,%2,%3}, {%4,%5,%6,%7}, {%8,%9}, {%0,%1,%2,%3};\n"
        : "+f"(c[0]), "+f"(c[1]), "+f"(c[2]), "+f"(c[3])
        : "r"(a[0]), "r"(a[1]), "r"(a[2]), "r"(a[3]),
          "r"(b[0]), "r"(b[1]));
}

#define CP_ASYNC16(dst_u32, src_ptr) \
    asm volatile("cp.async.cg.shared.global [%0], [%1], 16;\n" \
                 :: "r"(dst_u32), "l"(src_ptr) : "memory")
#define CP_COMMIT() asm volatile("cp.async.commit_group;\n" ::: "memory")
#define CP_WAIT0()  asm volatile("cp.async.wait_group 0;\n" ::: "memory")
#define CP_WAIT1()  asm volatile("cp.async.wait_group 1;\n" ::: "memory")

__device__ __forceinline__ uint32_t smem_u32(const void* p) {
    uint32_t a;
    asm("{ .reg .u64 t; cvta.to.shared.u64 t, %1; cvt.u32.u64 %0, t; }"
        : "=r"(a) : "l"(p));
    return a;
}

// ============================================================================
// TF32 tensor-core GEMM: C[M,N] = scale * (A[M,K] @ B[N,K]^T) + bias[N]
// tf32_out != 0 -> store outputs pre-rounded to tf32 (consumed raw by attn).
// ============================================================================
#define GBM 128
#define GBN 128
#define GBK 32
#define GSTRIDE 36

__global__ __launch_bounds__(256)
void gemm_tf32(const float* __restrict__ A, const float* __restrict__ B,
               float* __restrict__ C, int M, int N, int K,
               float scale, const float* __restrict__ bias, int tf32_out)
{
    __shared__ uint32_t As[GBM * GSTRIDE];
    __shared__ uint32_t Bs[GBN * GSTRIDE];

    const int tid  = threadIdx.x;
    const int lane = tid & 31;
    const int warp = tid >> 5;
    const int warp_m = warp >> 1;
    const int warp_n = warp & 1;
    const int row0 = blockIdx.y * GBM;
    const int col0 = blockIdx.x * GBN;

    const int ldr = tid >> 3;
    const int ldc = (tid & 7) << 2;

    float acc[2][8][4];
#pragma unroll
    for (int i = 0; i < 2; i++)
#pragma unroll
        for (int j = 0; j < 8; j++)
#pragma unroll
            for (int c = 0; c < 4; c++) acc[i][j][c] = 0.f;

    float4 pa[4], pb[4];

#pragma unroll
    for (int i = 0; i < 4; i++) {
        pa[i] = *(const float4*)(A + (size_t)(row0 + ldr + 32 * i) * K + ldc);
        pb[i] = *(const float4*)(B + (size_t)(col0 + ldr + 32 * i) * K + ldc);
    }
#pragma unroll
    for (int i = 0; i < 4; i++) {
        const int r = ldr + 32 * i;
        As[r * GSTRIDE + ldc + 0] = f2tf32(pa[i].x);
        As[r * GSTRIDE + ldc + 1] = f2tf32(pa[i].y);
        As[r * GSTRIDE + ldc + 2] = f2tf32(pa[i].z);
        As[r * GSTRIDE + ldc + 3] = f2tf32(pa[i].w);
        Bs[r * GSTRIDE + ldc + 0] = f2tf32(pb[i].x);
        Bs[r * GSTRIDE + ldc + 1] = f2tf32(pb[i].y);
        Bs[r * GSTRIDE + ldc + 2] = f2tf32(pb[i].z);
        Bs[r * GSTRIDE + ldc + 3] = f2tf32(pb[i].w);
    }
    __syncthreads();

    for (int k0 = 0; k0 < K; k0 += GBK) {
        const bool has_next = (k0 + GBK) < K;
        if (has_next) {
#pragma unroll
            for (int i = 0; i < 4; i++) {
                pa[i] = *(const float4*)(A + (size_t)(row0 + ldr + 32 * i) * K + k0 + GBK + ldc);
                pb[i] = *(const float4*)(B + (size_t)(col0 + ldr + 32 * i) * K + k0 + GBK + ldc);
            }
        }

#pragma unroll
        for (int ks = 0; ks < 4; ks++) {
            const int kk = ks * 8 + (lane & 3);
            uint32_t afrag[2][4];
#pragma unroll
            for (int tm = 0; tm < 2; tm++) {
                const int r = warp_m * 32 + tm * 16 + (lane >> 2);
                afrag[tm][0] = As[r * GSTRIDE + kk];
                afrag[tm][1] = As[(r + 8) * GSTRIDE + kk];
                afrag[tm][2] = As[r * GSTRIDE + kk + 4];
                afrag[tm][3] = As[(r + 8) * GSTRIDE + kk + 4];
            }
            uint32_t bfrag[8][2];
#pragma unroll
            for (int tn = 0; tn < 8; tn++) {
                const int n = warp_n * 64 + tn * 8 + (lane >> 2);
                bfrag[tn][0] = Bs[n * GSTRIDE + kk];
                bfrag[tn][1] = Bs[n * GSTRIDE + kk + 4];
            }
#pragma unroll
            for (int tm = 0; tm < 2; tm++)
#pragma unroll
                for (int tn = 0; tn < 8; tn++)
                    mma_tf32(acc[tm][tn], afrag[tm], bfrag[tn]);
        }

        if (has_next) {
            __syncthreads();
#pragma unroll
            for (int i = 0; i < 4; i++) {
                const int r = ldr + 32 * i;
                As[r * GSTRIDE + ldc + 0] = f2tf32(pa[i].x);
                As[r * GSTRIDE + ldc + 1] = f2tf32(pa[i].y);
                As[r * GSTRIDE + ldc + 2] = f2tf32(pa[i].z);
                As[r * GSTRIDE + ldc + 3] = f2tf32(pa[i].w);
                Bs[r * GSTRIDE + ldc + 0] = f2tf32(pb[i].x);
                Bs[r * GSTRIDE + ldc + 1] = f2tf32(pb[i].y);
                Bs[r * GSTRIDE + ldc + 2] = f2tf32(pb[i].z);
                Bs[r * GSTRIDE + ldc + 3] = f2tf32(pb[i].w);
            }
            __syncthreads();
        }
    }

#pragma unroll
    for (int tm = 0; tm < 2; tm++) {
#pragma unroll
        for (int tn = 0; tn < 8; tn++) {
            const int r = row0 + warp_m * 32 + tm * 16 + (lane >> 2);
            const int c = col0 + warp_n * 64 + tn * 8 + ((lane & 3) << 1);
            const float b0 = bias ? bias[c]     : 0.f;
            const float b1 = bias ? bias[c + 1] : 0.f;
            float2 v0, v1;
            v0.x = acc[tm][tn][0] * scale + b0;
            v0.y = acc[tm][tn][1] * scale + b1;
            v1.x = acc[tm][tn][2] * scale + b0;
            v1.y = acc[tm][tn][3] * scale + b1;
            if (tf32_out) {
                v0.x = __uint_as_float(f2tf32(v0.x));
                v0.y = __uint_as_float(f2tf32(v0.y));
                v1.x = __uint_as_float(f2tf32(v1.x));
                v1.y = __uint_as_float(f2tf32(v1.y));
            }
            *(float2*)(C + (size_t)r * N + c)       = v0;
            *(float2*)(C + (size_t)(r + 8) * N + c) = v1;
        }
    }
}

// ============================================================================
// TF32 tensor-core flash attention, cp.async pipelined, zero in-loop cvt
// (Q/K/V arrive pre-rounded to tf32 from the projection GEMMs).
// Block = 64 query rows of one (b,h). 128 threads = 4 warps, 16 rows/warp.
// Smem: 3 buffers of 64x72 words (K, V, Q->P) = 55296 B -> 4 CTAs/SM.
// Schedule per tile i:  wait K(i) -> sync -> issue V(i) -> S-loop ->
//   sync -> issue K(i+1) -> softmax -> wait V(i) -> sync -> PV.
// ============================================================================
#define FST 72
#define FTILE (64 * FST)
#define FA_SMEM (3 * FTILE * 4)           // 55296 bytes

__global__ __launch_bounds__(128, 4)
void flash_attn_tc(const float* __restrict__ Q, const float* __restrict__ K,
                   const float* __restrict__ V, float* __restrict__ O)
{
    extern __shared__ uint32_t usm[];
    uint32_t* Kb = usm;
    uint32_t* Vs = usm + FTILE;
    uint32_t* QP = usm + 2 * FTILE;       // Q tile, then P tile

    const int b  = blockIdx.z;
    const int h  = blockIdx.y;
    const int q0 = blockIdx.x * 64;

    const float* Qg = Q + (size_t)b * SEQ * DIM + h * DHEAD;
    const float* Kg = K + (size_t)b * SEQ * DIM + h * DHEAD;
    const float* Vg = V + (size_t)b * SEQ * DIM + h * DHEAD;
    float*       Og = O + (size_t)b * SEQ * DIM + h * DHEAD;

    const int tid  = threadIdx.x;
    const int lane = tid & 31;
    const int warp = tid >> 5;
    const int g = lane >> 2;
    const int t = lane & 3;
    const int wrow = warp * 16;

    const int sr = tid >> 4;            // 0..7
    const int sc = (tid & 15) << 2;     // 0..60 step 4

    const uint32_t k_u32 = smem_u32(Kb);
    const uint32_t v_u32 = smem_u32(Vs);

    // ---- prefetch K tile 0 ----
#pragma unroll
    for (int it = 0; it < 8; it++) {
        const int r = sr + it * 8;
        CP_ASYNC16(k_u32 + (r * FST + sc) * 4, Kg + (size_t)r * DIM + sc);
    }
    CP_COMMIT();

    // ---- stage Q tile (raw copy — already tf32 bits) ----
    const uint32_t* Qgu = (const uint32_t*)Qg;
#pragma unroll
    for (int it = 0; it < 8; it++) {
        const int r = sr + it * 8;
        uint4 v4 = *(const uint4*)(Qgu + (size_t)(q0 + r) * DIM + sc);
        QP[r * FST + sc + 0] = v4.x;
        QP[r * FST + sc + 1] = v4.y;
        QP[r * FST + sc + 2] = v4.z;
        QP[r * FST + sc + 3] = v4.w;
    }
    __syncthreads();

    // ---- hoist Q fragments ----
    uint32_t qf[8][4];
#pragma unroll
    for (int ks = 0; ks < 8; ks++) {
        const int kk = ks * 8 + t;
        qf[ks][0] = QP[(wrow + g) * FST + kk];
        qf[ks][1] = QP[(wrow + g + 8) * FST + kk];
        qf[ks][2] = QP[(wrow + g) * FST + kk + 4];
        qf[ks][3] = QP[(wrow + g + 8) * FST + kk + 4];
    }

    float oacc[8][4];
#pragma unroll
    for (int j = 0; j < 8; j++)
#pragma unroll
        for (int c = 0; c < 4; c++) oacc[j][c] = 0.f;
    float m_lo = -INFINITY, m_hi = -INFINITY;
    float l_lo = 0.f, l_hi = 0.f;

    const int NT = SEQ / 64;   // 32
    for (int ti = 0; ti < NT; ti++) {
        CP_WAIT0();            // K(ti) landed (and all older groups)
        __syncthreads();       // K visible; prev PV done -> V buffer free

        // issue V(ti)
#pragma unroll
        for (int it = 0; it < 8; it++) {
            const int r = sr + it * 8;
            CP_ASYNC16(v_u32 + (r * FST + sc) * 4,
                       Vg + (size_t)(ti * 64 + r) * DIM + sc);
        }
        CP_COMMIT();

        // ---- S = Q @ K^T ----
        float sacc[8][4];
#pragma unroll
        for (int j = 0; j < 8; j++)
#pragma unroll
            for (int c = 0; c < 4; c++) sacc[j][c] = 0.f;

#pragma unroll
        for (int ks = 0; ks < 8; ks++) {
            const int kk = ks * 8 + t;
            uint32_t bf[8][2];
#pragma unroll
            for (int j = 0; j < 8; j++) {
                bf[j][0] = Kb[(j * 8 + g) * FST + kk];
                bf[j][1] = Kb[(j * 8 + g) * FST + kk + 4];
            }
#pragma unroll
            for (int j = 0; j < 8; j++)
                mma_tf32(sacc[j], qf[ks], bf[j]);
        }
        __syncthreads();       // all warps done reading K(ti)

        // issue K(ti+1) into the same K buffer
        if (ti + 1 < NT) {
#pragma unroll
            for (int it = 0; it < 8; it++) {
                const int r = sr + it * 8;
                CP_ASYNC16(k_u32 + (r * FST + sc) * 4,
                           Kg + (size_t)((ti + 1) * 64 + r) * DIM + sc);
            }
        }
        CP_COMMIT();

        // ---- online softmax ----
        float mx_lo = -INFINITY, mx_hi = -INFINITY;
#pragma unroll
        for (int j = 0; j < 8; j++) {
            mx_lo = fmaxf(mx_lo, fmaxf(sacc[j][0], sacc[j][1]));
            mx_hi = fmaxf(mx_hi, fmaxf(sacc[j][2], sacc[j][3]));
        }
        mx_lo = fmaxf(mx_lo, __shfl_xor_sync(0xffffffffu, mx_lo, 1));
        mx_lo = fmaxf(mx_lo, __shfl_xor_sync(0xffffffffu, mx_lo, 2));
        mx_hi = fmaxf(mx_hi, __shfl_xor_sync(0xffffffffu, mx_hi, 1));
        mx_hi = fmaxf(mx_hi, __shfl_xor_sync(0xffffffffu, mx_hi, 2));

        const float mnew_lo = fmaxf(m_lo, mx_lo);
        const float mnew_hi = fmaxf(m_hi, mx_hi);
        const float corr_lo = __expf(m_lo - mnew_lo);
        const float corr_hi = __expf(m_hi - mnew_hi);
        m_lo = mnew_lo; m_hi = mnew_hi;

        float sum_lo = 0.f, sum_hi = 0.f;
#pragma unroll
        for (int j = 0; j < 8; j++) {
            const float p0 = __expf(sacc[j][0] - mnew_lo);
            const float p1 = __expf(sacc[j][1] - mnew_lo);
            const float p2 = __expf(sacc[j][2] - mnew_hi);
            const float p3 = __expf(sacc[j][3] - mnew_hi);
            sum_lo += p0 + p1;
            sum_hi += p2 + p3;
            uint2 plo, phi;
            plo.x = f2tf32(p0); plo.y = f2tf32(p1);
            phi.x = f2tf32(p2); phi.y = f2tf32(p3);
            *(uint2*)(QP + (wrow + g) * FST + j * 8 + 2 * t)     = plo;
            *(uint2*)(QP + (wrow + g + 8) * FST + j * 8 + 2 * t) = phi;
        }
        sum_lo += __shfl_xor_sync(0xffffffffu, sum_lo, 1);
        sum_lo += __shfl_xor_sync(0xffffffffu, sum_lo, 2);
        sum_hi += __shfl_xor_sync(0xffffffffu, sum_hi, 1);
        sum_hi += __shfl_xor_sync(0xffffffffu, sum_hi, 2);
        l_lo = l_lo * corr_lo + sum_lo;
        l_hi = l_hi * corr_hi + sum_hi;

#pragma unroll
        for (int j = 0; j < 8; j++) {
            oacc[j][0] *= corr_lo; oacc[j][1] *= corr_lo;
            oacc[j][2] *= corr_hi; oacc[j][3] *= corr_hi;
        }

        CP_WAIT1();            // V(ti) landed (K(ti+1) may still fly)
        __syncthreads();

        // ---- O += P @ V ----
#pragma unroll
        for (int ks = 0; ks < 8; ks++) {
            const int kk = ks * 8 + t;
            uint32_t af[4];
            af[0] = QP[(wrow + g) * FST + kk];
            af[1] = QP[(wrow + g + 8) * FST + kk];
            af[2] = QP[(wrow + g) * FST + kk + 4];
            af[3] = QP[(wrow + g + 8) * FST + kk + 4];
            uint32_t bf[8][2];
#pragma unroll
            for (int j = 0; j < 8; j++) {
                bf[j][0] = Vs[(ks * 8 + t) * FST + j * 8 + g];
                bf[j][1] = Vs[(ks * 8 + t + 4) * FST + j * 8 + g];
            }
#pragma unroll
            for (int j = 0; j < 8; j++)
                mma_tf32(oacc[j], af, bf[j]);
        }
    }

    // ---- epilogue ----
    const float inv_lo = 1.f / l_lo;
    const float inv_hi = 1.f / l_hi;
    const int r_lo = q0 + wrow + g;
    const int r_hi = r_lo + 8;
#pragma unroll
    for (int j = 0; j < 8; j++) {
        const int c = j * 8 + 2 * t;
        float2 vlo, vhi;
        vlo.x = oacc[j][0] * inv_lo; vlo.y = oacc[j][1] * inv_lo;
        vhi.x = oacc[j][2] * inv_hi; vhi.y = oacc[j][3] * inv_hi;
        *(float2*)(Og + (size_t)r_lo * DIM + c) = vlo;
        *(float2*)(Og + (size_t)r_hi * DIM + c) = vhi;
    }
}

// ============================================================================
// kernel_launch
// ============================================================================
extern "C" void kernel_launch(void* const* d_in, const int* in_sizes, int n_in,
                              void* d_out, int out_size)
{
    const float* x   = (const float*)d_in[0];
    const float* Wq  = (const float*)d_in[1];
    const float* Wk  = (const float*)d_in[2];
    const float* Wv  = (const float*)d_in[3];
    const float* Wff = (const float*)d_in[4];
    const float* bff = (const float*)d_in[5];
    float* out = (float*)d_out;

    float *q, *k, *v, *attn;
    cudaGetSymbolAddress((void**)&q,    g_q);
    cudaGetSymbolAddress((void**)&k,    g_k);
    cudaGetSymbolAddress((void**)&v,    g_v);
    cudaGetSymbolAddress((void**)&attn, g_attn);

    cudaFuncSetAttribute(flash_attn_tc,
                         cudaFuncAttributeMaxDynamicSharedMemorySize, FA_SMEM);

    dim3 gemm_grid(DIM / GBN, MROWS / GBM);   // (8, 32)
    const float qscale = 1.0f / 32.0f;        // 1/sqrt(1024)

    gemm_tf32<<<gemm_grid, 256>>>(x, Wq, q, MROWS, DIM, DIM, qscale, nullptr, 1);
    gemm_tf32<<<gemm_grid, 256>>>(x, Wk, k, MROWS, DIM, DIM, 1.0f, nullptr, 1);
    gemm_tf32<<<gemm_grid, 256>>>(x, Wv, v, MROWS, DIM, DIM, 1.0f, nullptr, 1);

    dim3 att_grid(SEQ / 64, HEADS, BATCH);    // (32, 16, 2)
    flash_attn_tc<<<att_grid, 128, FA_SMEM>>>(q, k, v, attn);

    gemm_tf32<<<gemm_grid, 256>>>(attn, Wff, out, MROWS, DIM, DIM, 1.0f, bff, 0);
}

// round 10
// speedup vs baseline: 1.4057x; 1.2639x over previous
#include <cuda_runtime.h>
#include <cuda_fp16.h>
#include <math.h>
#include <stdint.h>
#include <string.h>

// Problem constants (fixed by reference setup_inputs)
#define BATCH 2
#define SEQ   2048
#define DIM   1024
#define HEADS 16
#define DHEAD 64
#define MROWS (BATCH * SEQ)   // 4096

// -------- device scratch ----------------------------------------------------
__device__ __half g_qh[MROWS * DIM];
__device__ __half g_kh[MROWS * DIM];
__device__ __half g_vh[MROWS * DIM];
__device__ __half g_vt[MROWS * DIM];     // V transposed per batch: [b][d][s]
__device__ float  g_attn[MROWS * DIM];

__device__ __forceinline__ uint32_t f2tf32(float f) {
    uint32_t r;
    asm("cvt.rna.tf32.f32 %0, %1;" : "=r"(r) : "f"(f));
    return r;
}

__device__ __forceinline__ uint32_t h2_as_u32(__half2 h) {
    uint32_t u;
    memcpy(&u, &h, 4);
    return u;
}

__device__ __forceinline__ void mma_tf32(float c[4], const uint32_t a[4],
                                         const uint32_t b[2]) {
    asm volatile(
        "mma.sync.aligned.m16n8k8.row.col.f32.tf32.tf32.f32 "
        "{%0,%1,%2,%3}, {%4,%5,%6,%7}, {%8,%9}, {%0,%1,%2,%3};\n"
        : "+f"(c[0]), "+f"(c[1]), "+f"(c[2]), "+f"(c[3])
        : "r"(a[0]), "r"(a[1]), "r"(a[2]), "r"(a[3]),
          "r"(b[0]), "r"(b[1]));
}

__device__ __forceinline__ void mma_f16(float c[4], const uint32_t a[4],
                                        const uint32_t b[2]) {
    asm volatile(
        "mma.sync.aligned.m16n8k16.row.col.f32.f16.f16.f32 "
        "{%0,%1,%2,%3}, {%4,%5,%6,%7}, {%8,%9}, {%0,%1,%2,%3};\n"
        : "+f"(c[0]), "+f"(c[1]), "+f"(c[2]), "+f"(c[3])
        : "r"(a[0]), "r"(a[1]), "r"(a[2]), "r"(a[3]),
          "r"(b[0]), "r"(b[1]));
}

#define CP_ASYNC16(dst_u32, src_ptr) \
    asm volatile("cp.async.cg.shared.global [%0], [%1], 16;\n" \
                 :: "r"(dst_u32), "l"(src_ptr) : "memory")
#define CP_COMMIT() asm volatile("cp.async.commit_group;\n" ::: "memory")
#define CP_WAIT0()  asm volatile("cp.async.wait_group 0;\n" ::: "memory")

__device__ __forceinline__ uint32_t smem_u32(const void* p) {
    uint32_t a;
    asm("{ .reg .u64 t; cvta.to.shared.u64 t, %1; cvt.u32.u64 %0, t; }"
        : "=r"(a) : "l"(p));
    return a;
}

// ============================================================================
// TF32 tensor-core GEMM: C[M,N] = scale * (A[M,K] @ B[N,K]^T) + bias[N]
// out_half: 1 -> store __half row-major; 0 -> fp32.
// ============================================================================
#define GBM 128
#define GBN 128
#define GBK 32
#define GSTRIDE 36

__global__ __launch_bounds__(256)
void gemm_tf32(const float* __restrict__ A, const float* __restrict__ B,
               void* __restrict__ Cv, int M, int N, int K,
               float scale, const float* __restrict__ bias, int out_half)
{
    __shared__ uint32_t As[GBM * GSTRIDE];
    __shared__ uint32_t Bs[GBN * GSTRIDE];

    const int tid  = threadIdx.x;
    const int lane = tid & 31;
    const int warp = tid >> 5;
    const int warp_m = warp >> 1;
    const int warp_n = warp & 1;
    const int row0 = blockIdx.y * GBM;
    const int col0 = blockIdx.x * GBN;

    const int ldr = tid >> 3;
    const int ldc = (tid & 7) << 2;

    float acc[2][8][4];
#pragma unroll
    for (int i = 0; i < 2; i++)
#pragma unroll
        for (int j = 0; j < 8; j++)
#pragma unroll
            for (int c = 0; c < 4; c++) acc[i][j][c] = 0.f;

    float4 pa[4], pb[4];

#pragma unroll
    for (int i = 0; i < 4; i++) {
        pa[i] = *(const float4*)(A + (size_t)(row0 + ldr + 32 * i) * K + ldc);
        pb[i] = *(const float4*)(B + (size_t)(col0 + ldr + 32 * i) * K + ldc);
    }
#pragma unroll
    for (int i = 0; i < 4; i++) {
        const int r = ldr + 32 * i;
        As[r * GSTRIDE + ldc + 0] = f2tf32(pa[i].x);
        As[r * GSTRIDE + ldc + 1] = f2tf32(pa[i].y);
        As[r * GSTRIDE + ldc + 2] = f2tf32(pa[i].z);
        As[r * GSTRIDE + ldc + 3] = f2tf32(pa[i].w);
        Bs[r * GSTRIDE + ldc + 0] = f2tf32(pb[i].x);
        Bs[r * GSTRIDE + ldc + 1] = f2tf32(pb[i].y);
        Bs[r * GSTRIDE + ldc + 2] = f2tf32(pb[i].z);
        Bs[r * GSTRIDE + ldc + 3] = f2tf32(pb[i].w);
    }
    __syncthreads();

    for (int k0 = 0; k0 < K; k0 += GBK) {
        const bool has_next = (k0 + GBK) < K;
        if (has_next) {
#pragma unroll
            for (int i = 0; i < 4; i++) {
                pa[i] = *(const float4*)(A + (size_t)(row0 + ldr + 32 * i) * K + k0 + GBK + ldc);
                pb[i] = *(const float4*)(B + (size_t)(col0 + ldr + 32 * i) * K + k0 + GBK + ldc);
            }
        }

#pragma unroll
        for (int ks = 0; ks < 4; ks++) {
            const int kk = ks * 8 + (lane & 3);
            uint32_t afrag[2][4];
#pragma unroll
            for (int tm = 0; tm < 2; tm++) {
                const int r = warp_m * 32 + tm * 16 + (lane >> 2);
                afrag[tm][0] = As[r * GSTRIDE + kk];
                afrag[tm][1] = As[(r + 8) * GSTRIDE + kk];
                afrag[tm][2] = As[r * GSTRIDE + kk + 4];
                afrag[tm][3] = As[(r + 8) * GSTRIDE + kk + 4];
            }
            uint32_t bfrag[8][2];
#pragma unroll
            for (int tn = 0; tn < 8; tn++) {
                const int n = warp_n * 64 + tn * 8 + (lane >> 2);
                bfrag[tn][0] = Bs[n * GSTRIDE + kk];
                bfrag[tn][1] = Bs[n * GSTRIDE + kk + 4];
            }
#pragma unroll
            for (int tm = 0; tm < 2; tm++)
#pragma unroll
                for (int tn = 0; tn < 8; tn++)
                    mma_tf32(acc[tm][tn], afrag[tm], bfrag[tn]);
        }

        if (has_next) {
            __syncthreads();
#pragma unroll
            for (int i = 0; i < 4; i++) {
                const int r = ldr + 32 * i;
                As[r * GSTRIDE + ldc + 0] = f2tf32(pa[i].x);
                As[r * GSTRIDE + ldc + 1] = f2tf32(pa[i].y);
                As[r * GSTRIDE + ldc + 2] = f2tf32(pa[i].z);
                As[r * GSTRIDE + ldc + 3] = f2tf32(pa[i].w);
                Bs[r * GSTRIDE + ldc + 0] = f2tf32(pb[i].x);
                Bs[r * GSTRIDE + ldc + 1] = f2tf32(pb[i].y);
                Bs[r * GSTRIDE + ldc + 2] = f2tf32(pb[i].z);
                Bs[r * GSTRIDE + ldc + 3] = f2tf32(pb[i].w);
            }
            __syncthreads();
        }
    }

#pragma unroll
    for (int tm = 0; tm < 2; tm++) {
#pragma unroll
        for (int tn = 0; tn < 8; tn++) {
            const int r = row0 + warp_m * 32 + tm * 16 + (lane >> 2);
            const int c = col0 + warp_n * 64 + tn * 8 + ((lane & 3) << 1);
            const float b0 = bias ? bias[c]     : 0.f;
            const float b1 = bias ? bias[c + 1] : 0.f;
            float2 v0, v1;
            v0.x = acc[tm][tn][0] * scale + b0;
            v0.y = acc[tm][tn][1] * scale + b1;
            v1.x = acc[tm][tn][2] * scale + b0;
            v1.y = acc[tm][tn][3] * scale + b1;
            if (out_half) {
                __half* Ch = (__half*)Cv;
                *(__half2*)(Ch + (size_t)r * N + c)       = __floats2half2_rn(v0.x, v0.y);
                *(__half2*)(Ch + (size_t)(r + 8) * N + c) = __floats2half2_rn(v1.x, v1.y);
            } else {
                float* C = (float*)Cv;
                *(float2*)(C + (size_t)r * N + c)       = v0;
                *(float2*)(C + (size_t)(r + 8) * N + c) = v1;
            }
        }
    }
}

// ============================================================================
// Transpose V per (b,h): Vt[b][h*64+d][s] = Vh[b][s][h*64+d]. half -> half.
// ============================================================================
__global__ __launch_bounds__(128)
void transpose_v(const __half* __restrict__ Vh, __half* __restrict__ Vt)
{
    __shared__ __half sm[64][72];
    const int b  = blockIdx.z;
    const int h  = blockIdx.y;
    const int s0 = blockIdx.x * 64;
    const int tid = threadIdx.x;

#pragma unroll
    for (int it = 0; it < 16; it++) {
        const int idx = tid + it * 128;          // 2048 uints
        const int r  = idx >> 5;                 // s-row 0..63
        const int cu = idx & 31;                 // uint col (2 halves)
        *(uint32_t*)&sm[r][cu * 2] =
            *(const uint32_t*)&Vh[((size_t)(b * SEQ + s0 + r)) * DIM + h * 64 + cu * 2];
    }
    __syncthreads();

#pragma unroll
    for (int it = 0; it < 16; it++) {
        const int idx = tid + it * 128;
        const int d  = idx >> 5;                 // dim row 0..63
        const int su = idx & 31;                 // s uint col
        __half2 hv;
        hv.x = sm[2 * su][d];
        hv.y = sm[2 * su + 1][d];
        *(__half2*)&Vt[((size_t)(b * DIM + h * 64 + d)) * SEQ + s0 + 2 * su] = hv;
    }
}

// ============================================================================
// FP16 tensor-core flash attention (FA2-style, P stays in registers).
// Block = 64 query rows of one (b,h). 128 threads = 4 warps, 16 rows/warp.
// Smem: K double buffer + V^T double buffer, each 64 rows x 144B (pitch 36
// uints -> bank = (4g+t) mod 32, conflict-free gathers). Total 36864 B.
// Schedule (ONE cp.async group outstanding at a time):
//   iter ti: CP_WAIT0 (G(ti) landed) -> __syncthreads (prior PV done, both
//   visibility + WAR protection) -> issue G(ti+1) into nxt -> S/softmax/PV
//   on cur while G(ti+1) flies.
// ============================================================================
#define PU 36                         // uints per smem row (144 B)
#define HTILE (64 * PU)               // uints per buffer
#define FA_SMEM (4 * HTILE * 4)       // 36864 bytes

__global__ __launch_bounds__(128, 4)
void flash_attn_f16(const __half* __restrict__ Qh, const __half* __restrict__ Kh,
                    const __half* __restrict__ Vt, float* __restrict__ O)
{
    extern __shared__ uint32_t usm[];
    uint32_t* Kb[2] = { usm,             usm + HTILE };
    uint32_t* Vb[2] = { usm + 2 * HTILE, usm + 3 * HTILE };

    const int b  = blockIdx.z;
    const int h  = blockIdx.y;
    const int q0 = blockIdx.x * 64;

    const int tid  = threadIdx.x;
    const int lane = tid & 31;
    const int warp = tid >> 5;
    const int g = lane >> 2;
    const int t = lane & 3;
    const int wrow = warp * 16;

    const uint32_t kb_u32[2] = { smem_u32(Kb[0]), smem_u32(Kb[1]) };
    const uint32_t vb_u32[2] = { smem_u32(Vb[0]), smem_u32(Vb[1]) };

    const __half* Kg  = Kh + ((size_t)b * SEQ) * DIM + h * 64;
    const __half* Vtg = Vt + ((size_t)b * DIM + h * 64) * SEQ;

    // ---- issue K(0), V(0) as group 0 ----
#pragma unroll
    for (int it = 0; it < 4; it++) {
        const int c = tid + it * 128;
        const int row = c >> 3, ch = c & 7;
        CP_ASYNC16(kb_u32[0] + row * PU * 4 + ch * 16,
                   (const char*)(Kg + (size_t)row * DIM) + ch * 16);
    }
#pragma unroll
    for (int it = 0; it < 4; it++) {
        const int c = tid + it * 128;
        const int row = c >> 3, ch = c & 7;
        CP_ASYNC16(vb_u32[0] + row * PU * 4 + ch * 16,
                   (const char*)(Vtg + (size_t)row * SEQ) + ch * 16);
    }
    CP_COMMIT();

    // ---- Q fragments straight from gmem: qf[4 kchunks][4] ----
    uint32_t qf[4][4];
#pragma unroll
    for (int ks = 0; ks < 4; ks++) {
        const size_t rlo = (size_t)(b * SEQ + q0 + wrow + g) * DIM + h * 64 + ks * 16 + 2 * t;
        const size_t rhi = rlo + 8 * DIM;
        qf[ks][0] = *(const uint32_t*)(Qh + rlo);
        qf[ks][1] = *(const uint32_t*)(Qh + rhi);
        qf[ks][2] = *(const uint32_t*)(Qh + rlo + 8);
        qf[ks][3] = *(const uint32_t*)(Qh + rhi + 8);
    }

    float oacc[8][4];
#pragma unroll
    for (int j = 0; j < 8; j++)
#pragma unroll
        for (int c = 0; c < 4; c++) oacc[j][c] = 0.f;
    float m_lo = -INFINITY, m_hi = -INFINITY;
    float l_lo = 0.f, l_hi = 0.f;

    const int NT = SEQ / 64;   // 32
    for (int ti = 0; ti < NT; ti++) {
        const int cur = ti & 1, nxt = cur ^ 1;

        CP_WAIT0();            // G(ti) landed (only group outstanding)
        __syncthreads();       // data visible to all warps; ALL warps past
                               // prior PV -> nxt buffers safe to overwrite

        // issue K/V(ti+1) into the other buffers
        if (ti + 1 < NT) {
            const __half* Kg1  = Kg + (size_t)(ti + 1) * 64 * DIM;
            const __half* Vtg1 = Vtg + (size_t)(ti + 1) * 64;
#pragma unroll
            for (int it = 0; it < 4; it++) {
                const int c = tid + it * 128;
                const int row = c >> 3, ch = c & 7;
                CP_ASYNC16(kb_u32[nxt] + row * PU * 4 + ch * 16,
                           (const char*)(Kg1 + (size_t)row * DIM) + ch * 16);
            }
#pragma unroll
            for (int it = 0; it < 4; it++) {
                const int c = tid + it * 128;
                const int row = c >> 3, ch = c & 7;
                CP_ASYNC16(vb_u32[nxt] + row * PU * 4 + ch * 16,
                           (const char*)(Vtg1 + (size_t)row * SEQ) + ch * 16);
            }
            CP_COMMIT();
        }

        const uint32_t* K_s = Kb[cur];
        const uint32_t* V_s = Vb[cur];

        // ---- S = Q @ K^T (f16 k16) ----
        float sacc[8][4];
#pragma unroll
        for (int j = 0; j < 8; j++)
#pragma unroll
            for (int c = 0; c < 4; c++) sacc[j][c] = 0.f;

#pragma unroll
        for (int ks = 0; ks < 4; ks++) {
#pragma unroll
            for (int j = 0; j < 8; j++) {
                uint32_t bf[2];
                bf[0] = K_s[(j * 8 + g) * PU + ks * 8 + t];
                bf[1] = K_s[(j * 8 + g) * PU + ks * 8 + t + 4];
                mma_f16(sacc[j], qf[ks], bf);
            }
        }

        // ---- online softmax ----
        float mx_lo = -INFINITY, mx_hi = -INFINITY;
#pragma unroll
        for (int j = 0; j < 8; j++) {
            mx_lo = fmaxf(mx_lo, fmaxf(sacc[j][0], sacc[j][1]));
            mx_hi = fmaxf(mx_hi, fmaxf(sacc[j][2], sacc[j][3]));
        }
        mx_lo = fmaxf(mx_lo, __shfl_xor_sync(0xffffffffu, mx_lo, 1));
        mx_lo = fmaxf(mx_lo, __shfl_xor_sync(0xffffffffu, mx_lo, 2));
        mx_hi = fmaxf(mx_hi, __shfl_xor_sync(0xffffffffu, mx_hi, 1));
        mx_hi = fmaxf(mx_hi, __shfl_xor_sync(0xffffffffu, mx_hi, 2));

        const float mnew_lo = fmaxf(m_lo, mx_lo);
        const float mnew_hi = fmaxf(m_hi, mx_hi);
        const float corr_lo = __expf(m_lo - mnew_lo);
        const float corr_hi = __expf(m_hi - mnew_hi);
        m_lo = mnew_lo; m_hi = mnew_hi;

        uint32_t ph_lo[8], ph_hi[8];   // packed P halves, rows g / g+8
        float sum_lo = 0.f, sum_hi = 0.f;
#pragma unroll
        for (int j = 0; j < 8; j++) {
            const float p0 = __expf(sacc[j][0] - mnew_lo);
            const float p1 = __expf(sacc[j][1] - mnew_lo);
            const float p2 = __expf(sacc[j][2] - mnew_hi);
            const float p3 = __expf(sacc[j][3] - mnew_hi);
            sum_lo += p0 + p1;
            sum_hi += p2 + p3;
            ph_lo[j] = h2_as_u32(__floats2half2_rn(p0, p1));
            ph_hi[j] = h2_as_u32(__floats2half2_rn(p2, p3));
        }
        sum_lo += __shfl_xor_sync(0xffffffffu, sum_lo, 1);
        sum_lo += __shfl_xor_sync(0xffffffffu, sum_lo, 2);
        sum_hi += __shfl_xor_sync(0xffffffffu, sum_hi, 1);
        sum_hi += __shfl_xor_sync(0xffffffffu, sum_hi, 2);
        l_lo = l_lo * corr_lo + sum_lo;
        l_hi = l_hi * corr_hi + sum_hi;

#pragma unroll
        for (int j = 0; j < 8; j++) {
            oacc[j][0] *= corr_lo; oacc[j][1] *= corr_lo;
            oacc[j][2] *= corr_hi; oacc[j][3] *= corr_hi;
        }

        // ---- O += P @ V (P from registers, V^T from smem) ----
#pragma unroll
        for (int ks = 0; ks < 4; ks++) {
            uint32_t af[4];
            af[0] = ph_lo[2 * ks];
            af[1] = ph_hi[2 * ks];
            af[2] = ph_lo[2 * ks + 1];
            af[3] = ph_hi[2 * ks + 1];
#pragma unroll
            for (int j = 0; j < 8; j++) {
                uint32_t bf[2];
                bf[0] = V_s[(j * 8 + g) * PU + ks * 8 + t];
                bf[1] = V_s[(j * 8 + g) * PU + ks * 8 + t + 4];
                mma_f16(oacc[j], af, bf);
            }
        }
        // next iter's CP_WAIT0 + __syncthreads gates buffer reuse.
    }

    // ---- epilogue ----
    float* Og = O + (size_t)b * SEQ * DIM + h * DHEAD;
    const float inv_lo = 1.f / l_lo;
    const float inv_hi = 1.f / l_hi;
    const int r_lo = q0 + wrow + g;
    const int r_hi = r_lo + 8;
#pragma unroll
    for (int j = 0; j < 8; j++) {
        const int c = j * 8 + 2 * t;
        float2 vlo, vhi;
        vlo.x = oacc[j][0] * inv_lo; vlo.y = oacc[j][1] * inv_lo;
        vhi.x = oacc[j][2] * inv_hi; vhi.y = oacc[j][3] * inv_hi;
        *(float2*)(Og + (size_t)r_lo * DIM + c) = vlo;
        *(float2*)(Og + (size_t)r_hi * DIM + c) = vhi;
    }
}

// ============================================================================
// kernel_launch
// ============================================================================
extern "C" void kernel_launch(void* const* d_in, const int* in_sizes, int n_in,
                              void* d_out, int out_size)
{
    const float* x   = (const float*)d_in[0];
    const float* Wq  = (const float*)d_in[1];
    const float* Wk  = (const float*)d_in[2];
    const float* Wv  = (const float*)d_in[3];
    const float* Wff = (const float*)d_in[4];
    const float* bff = (const float*)d_in[5];
    float* out = (float*)d_out;

    __half *qh, *kh, *vh, *vt;
    float *attn;
    cudaGetSymbolAddress((void**)&qh,   g_qh);
    cudaGetSymbolAddress((void**)&kh,   g_kh);
    cudaGetSymbolAddress((void**)&vh,   g_vh);
    cudaGetSymbolAddress((void**)&vt,   g_vt);
    cudaGetSymbolAddress((void**)&attn, g_attn);

    cudaFuncSetAttribute(flash_attn_f16,
                         cudaFuncAttributeMaxDynamicSharedMemorySize, FA_SMEM);

    dim3 gemm_grid(DIM / GBN, MROWS / GBM);   // (8, 32)
    const float qscale = 1.0f / 32.0f;        // 1/sqrt(1024)

    gemm_tf32<<<gemm_grid, 256>>>(x, Wq, qh, MROWS, DIM, DIM, qscale, nullptr, 1);
    gemm_tf32<<<gemm_grid, 256>>>(x, Wk, kh, MROWS, DIM, DIM, 1.0f, nullptr, 1);
    gemm_tf32<<<gemm_grid, 256>>>(x, Wv, vh, MROWS, DIM, DIM, 1.0f, nullptr, 1);

    dim3 tr_grid(SEQ / 64, HEADS, BATCH);
    transpose_v<<<tr_grid, 128>>>(vh, vt);

    dim3 att_grid(SEQ / 64, HEADS, BATCH);    // (32, 16, 2)
    flash_attn_f16<<<att_grid, 128, FA_SMEM>>>(qh, kh, vt, attn);

    gemm_tf32<<<gemm_grid, 256>>>(attn, Wff, out, MROWS, DIM, DIM, 1.0f, bff, 0);
}

// round 11
// speedup vs baseline: 1.8327x; 1.3038x over previous
#include <cuda_runtime.h>
#include <cuda_fp16.h>
#include <math.h>
#include <stdint.h>
#include <string.h>

// Problem constants (fixed by reference setup_inputs)
#define BATCH 2
#define SEQ   2048
#define DIM   1024
#define HEADS 16
#define DHEAD 64
#define MROWS (BATCH * SEQ)   // 4096

// -------- device scratch ----------------------------------------------------
__device__ __half g_xh[MROWS * DIM];
__device__ __half g_wq[DIM * DIM];
__device__ __half g_wk[DIM * DIM];
__device__ __half g_wv[DIM * DIM];
__device__ __half g_wf[DIM * DIM];
__device__ __half g_qh[MROWS * DIM];
__device__ __half g_kh[MROWS * DIM];
__device__ __half g_vh[MROWS * DIM];
__device__ __half g_vt[MROWS * DIM];     // V transposed per batch: [b][d][s]
__device__ __half g_attn[MROWS * DIM];

__device__ __forceinline__ uint32_t h2_as_u32(__half2 h) {
    uint32_t u;
    memcpy(&u, &h, 4);
    return u;
}

__device__ __forceinline__ void mma_f16(float c[4], const uint32_t a[4],
                                        const uint32_t b[2]) {
    asm volatile(
        "mma.sync.aligned.m16n8k16.row.col.f32.f16.f16.f32 "
        "{%0,%1,%2,%3}, {%4,%5,%6,%7}, {%8,%9}, {%0,%1,%2,%3};\n"
        : "+f"(c[0]), "+f"(c[1]), "+f"(c[2]), "+f"(c[3])
        : "r"(a[0]), "r"(a[1]), "r"(a[2]), "r"(a[3]),
          "r"(b[0]), "r"(b[1]));
}

#define CP_ASYNC16(dst_u32, src_ptr) \
    asm volatile("cp.async.cg.shared.global [%0], [%1], 16;\n" \
                 :: "r"(dst_u32), "l"(src_ptr) : "memory")
#define CP_COMMIT() asm volatile("cp.async.commit_group;\n" ::: "memory")
#define CP_WAIT0()  asm volatile("cp.async.wait_group 0;\n" ::: "memory")

__device__ __forceinline__ uint32_t smem_u32(const void* p) {
    uint32_t a;
    asm("{ .reg .u64 t; cvta.to.shared.u64 t, %1; cvt.u32.u64 %0, t; }"
        : "=r"(a) : "l"(p));
    return a;
}

// ============================================================================
// f32 -> f16 elementwise convert (n multiple of 4)
// ============================================================================
__global__ __launch_bounds__(256)
void f32_to_f16(const float* __restrict__ in, __half* __restrict__ out, int n)
{
    const int i = (blockIdx.x * 256 + threadIdx.x) * 4;
    if (i < n) {
        float4 v = *(const float4*)(in + i);
        *(__half2*)(out + i)     = __floats2half2_rn(v.x, v.y);
        *(__half2*)(out + i + 2) = __floats2half2_rn(v.z, v.w);
    }
}

// ============================================================================
// FP16 tensor-core GEMM: C[M,N] = scale * (A[M,K] @ B[N,K]^T) + bias[N]
// A,B fp16. out_half: 1 -> C fp16, 0 -> C fp32 (+bias).
// 128x128x32 tiles, 256 threads = 8 warps (4x2), warp tile 32x64.
// Smem: double-buffered A/B, pitch 20 uints/row (bank (20g+t)%32 distinct).
// cp.async pipeline: WAIT0 -> sync -> issue next -> compute (proven in attn).
// ============================================================================
#define HBM 128
#define HBN 128
#define HBK 32                       // halves per k-chunk
#define HPU 20                       // uints per smem row (80 B)
#define HT (128 * HPU)               // uints per tile buffer

__global__ __launch_bounds__(256)
void gemm_f16(const __half* __restrict__ A, const __half* __restrict__ B,
              void* __restrict__ Cv, int M, int N, int K,
              float scale, const float* __restrict__ bias, int out_half)
{
    __shared__ uint32_t sm[2][2 * HT];   // [buf][A tile | B tile]

    const int tid  = threadIdx.x;
    const int lane = tid & 31;
    const int warp = tid >> 5;
    const int warp_m = warp >> 1;        // 0..3
    const int warp_n = warp & 1;         // 0..1
    const int g = lane >> 2;
    const int t = lane & 3;
    const int row0 = blockIdx.y * HBM;
    const int col0 = blockIdx.x * HBN;

    const uint32_t sm_u32[2] = { smem_u32(sm[0]), smem_u32(sm[1]) };

    // staging: A tile = 128 rows x 4 chunks(16B) = 512 chunks; same for B.
    // thread covers 2 chunks of A + 2 of B.
    const int c0 = tid, c1 = tid + 256;
    const int ar0 = c0 >> 2, ac0 = c0 & 3;
    const int ar1 = c1 >> 2, ac1 = c1 & 3;

    const __half* Ag = A + (size_t)row0 * K;
    const __half* Bg = B + (size_t)col0 * K;

    // ---- issue tile 0 ----
    {
        CP_ASYNC16(sm_u32[0] + (ar0 * HPU) * 4 + ac0 * 16,
                   (const char*)(Ag + (size_t)ar0 * K) + ac0 * 16);
        CP_ASYNC16(sm_u32[0] + (ar1 * HPU) * 4 + ac1 * 16,
                   (const char*)(Ag + (size_t)ar1 * K) + ac1 * 16);
        CP_ASYNC16(sm_u32[0] + (HT + ar0 * HPU) * 4 + ac0 * 16,
                   (const char*)(Bg + (size_t)ar0 * K) + ac0 * 16);
        CP_ASYNC16(sm_u32[0] + (HT + ar1 * HPU) * 4 + ac1 * 16,
                   (const char*)(Bg + (size_t)ar1 * K) + ac1 * 16);
        CP_COMMIT();
    }

    float acc[2][8][4];
#pragma unroll
    for (int i = 0; i < 2; i++)
#pragma unroll
        for (int j = 0; j < 8; j++)
#pragma unroll
            for (int c = 0; c < 4; c++) acc[i][j][c] = 0.f;

    const int NI = K / HBK;   // 32
    for (int it = 0; it < NI; it++) {
        const int cur = it & 1, nxt = cur ^ 1;

        CP_WAIT0();
        __syncthreads();      // tile(it) visible; buffers nxt free (all warps
                              // finished compute on it-1)

        if (it + 1 < NI) {
            const int koff = (it + 1) * HBK;   // halves
            CP_ASYNC16(sm_u32[nxt] + (ar0 * HPU) * 4 + ac0 * 16,
                       (const char*)(Ag + (size_t)ar0 * K + koff) + ac0 * 16);
            CP_ASYNC16(sm_u32[nxt] + (ar1 * HPU) * 4 + ac1 * 16,
                       (const char*)(Ag + (size_t)ar1 * K + koff) + ac1 * 16);
            CP_ASYNC16(sm_u32[nxt] + (HT + ar0 * HPU) * 4 + ac0 * 16,
                       (const char*)(Bg + (size_t)ar0 * K + koff) + ac0 * 16);
            CP_ASYNC16(sm_u32[nxt] + (HT + ar1 * HPU) * 4 + ac1 * 16,
                       (const char*)(Bg + (size_t)ar1 * K + koff) + ac1 * 16);
            CP_COMMIT();
        }

        const uint32_t* As = sm[cur];
        const uint32_t* Bs = sm[cur] + HT;

#pragma unroll
        for (int ks = 0; ks < 2; ks++) {
            uint32_t afrag[2][4];
#pragma unroll
            for (int tm = 0; tm < 2; tm++) {
                const int r = warp_m * 32 + tm * 16 + g;
                afrag[tm][0] = As[r * HPU + ks * 8 + t];
                afrag[tm][1] = As[(r + 8) * HPU + ks * 8 + t];
                afrag[tm][2] = As[r * HPU + ks * 8 + t + 4];
                afrag[tm][3] = As[(r + 8) * HPU + ks * 8 + t + 4];
            }
            uint32_t bfrag[8][2];
#pragma unroll
            for (int tn = 0; tn < 8; tn++) {
                const int n = warp_n * 64 + tn * 8 + g;
                bfrag[tn][0] = Bs[n * HPU + ks * 8 + t];
                bfrag[tn][1] = Bs[n * HPU + ks * 8 + t + 4];
            }
#pragma unroll
            for (int tm = 0; tm < 2; tm++)
#pragma unroll
                for (int tn = 0; tn < 8; tn++)
                    mma_f16(acc[tm][tn], afrag[tm], bfrag[tn]);
        }
    }

    // ---- epilogue ----
#pragma unroll
    for (int tm = 0; tm < 2; tm++) {
#pragma unroll
        for (int tn = 0; tn < 8; tn++) {
            const int r = row0 + warp_m * 32 + tm * 16 + g;
            const int c = col0 + warp_n * 64 + tn * 8 + 2 * t;
            const float b0 = bias ? bias[c]     : 0.f;
            const float b1 = bias ? bias[c + 1] : 0.f;
            float2 v0, v1;
            v0.x = acc[tm][tn][0] * scale + b0;
            v0.y = acc[tm][tn][1] * scale + b1;
            v1.x = acc[tm][tn][2] * scale + b0;
            v1.y = acc[tm][tn][3] * scale + b1;
            if (out_half) {
                __half* Ch = (__half*)Cv;
                *(__half2*)(Ch + (size_t)r * N + c)       = __floats2half2_rn(v0.x, v0.y);
                *(__half2*)(Ch + (size_t)(r + 8) * N + c) = __floats2half2_rn(v1.x, v1.y);
            } else {
                float* C = (float*)Cv;
                *(float2*)(C + (size_t)r * N + c)       = v0;
                *(float2*)(C + (size_t)(r + 8) * N + c) = v1;
            }
        }
    }
}

// ============================================================================
// Transpose V per (b,h): Vt[b][h*64+d][s] = Vh[b][s][h*64+d]. half -> half.
// ============================================================================
__global__ __launch_bounds__(128)
void transpose_v(const __half* __restrict__ Vh, __half* __restrict__ Vt)
{
    __shared__ __half sm[64][72];
    const int b  = blockIdx.z;
    const int h  = blockIdx.y;
    const int s0 = blockIdx.x * 64;
    const int tid = threadIdx.x;

#pragma unroll
    for (int it = 0; it < 16; it++) {
        const int idx = tid + it * 128;
        const int r  = idx >> 5;
        const int cu = idx & 31;
        *(uint32_t*)&sm[r][cu * 2] =
            *(const uint32_t*)&Vh[((size_t)(b * SEQ + s0 + r)) * DIM + h * 64 + cu * 2];
    }
    __syncthreads();

#pragma unroll
    for (int it = 0; it < 16; it++) {
        const int idx = tid + it * 128;
        const int d  = idx >> 5;
        const int su = idx & 31;
        __half2 hv;
        hv.x = sm[2 * su][d];
        hv.y = sm[2 * su + 1][d];
        *(__half2*)&Vt[((size_t)(b * DIM + h * 64 + d)) * SEQ + s0 + 2 * su] = hv;
    }
}

// ============================================================================
// FP16 tensor-core flash attention (FA2-style, P stays in registers).
// Output written as fp16 (consumed by the fp16 FF GEMM).
// ============================================================================
#define PU 36                         // uints per smem row (144 B)
#define HTILE (64 * PU)               // uints per buffer
#define FA_SMEM (4 * HTILE * 4)       // 36864 bytes

__global__ __launch_bounds__(128, 4)
void flash_attn_f16(const __half* __restrict__ Qh, const __half* __restrict__ Kh,
                    const __half* __restrict__ Vt, __half* __restrict__ O)
{
    extern __shared__ uint32_t usm[];
    uint32_t* Kb[2] = { usm,             usm + HTILE };
    uint32_t* Vb[2] = { usm + 2 * HTILE, usm + 3 * HTILE };

    const int b  = blockIdx.z;
    const int h  = blockIdx.y;
    const int q0 = blockIdx.x * 64;

    const int tid  = threadIdx.x;
    const int lane = tid & 31;
    const int warp = tid >> 5;
    const int g = lane >> 2;
    const int t = lane & 3;
    const int wrow = warp * 16;

    const uint32_t kb_u32[2] = { smem_u32(Kb[0]), smem_u32(Kb[1]) };
    const uint32_t vb_u32[2] = { smem_u32(Vb[0]), smem_u32(Vb[1]) };

    const __half* Kg  = Kh + ((size_t)b * SEQ) * DIM + h * 64;
    const __half* Vtg = Vt + ((size_t)b * DIM + h * 64) * SEQ;

    // ---- issue K(0), V(0) as group 0 ----
#pragma unroll
    for (int it = 0; it < 4; it++) {
        const int c = tid + it * 128;
        const int row = c >> 3, ch = c & 7;
        CP_ASYNC16(kb_u32[0] + row * PU * 4 + ch * 16,
                   (const char*)(Kg + (size_t)row * DIM) + ch * 16);
    }
#pragma unroll
    for (int it = 0; it < 4; it++) {
        const int c = tid + it * 128;
        const int row = c >> 3, ch = c & 7;
        CP_ASYNC16(vb_u32[0] + row * PU * 4 + ch * 16,
                   (const char*)(Vtg + (size_t)row * SEQ) + ch * 16);
    }
    CP_COMMIT();

    // ---- Q fragments straight from gmem ----
    uint32_t qf[4][4];
#pragma unroll
    for (int ks = 0; ks < 4; ks++) {
        const size_t rlo = (size_t)(b * SEQ + q0 + wrow + g) * DIM + h * 64 + ks * 16 + 2 * t;
        const size_t rhi = rlo + 8 * DIM;
        qf[ks][0] = *(const uint32_t*)(Qh + rlo);
        qf[ks][1] = *(const uint32_t*)(Qh + rhi);
        qf[ks][2] = *(const uint32_t*)(Qh + rlo + 8);
        qf[ks][3] = *(const uint32_t*)(Qh + rhi + 8);
    }

    float oacc[8][4];
#pragma unroll
    for (int j = 0; j < 8; j++)
#pragma unroll
        for (int c = 0; c < 4; c++) oacc[j][c] = 0.f;
    float m_lo = -INFINITY, m_hi = -INFINITY;
    float l_lo = 0.f, l_hi = 0.f;

    const int NT = SEQ / 64;   // 32
    for (int ti = 0; ti < NT; ti++) {
        const int cur = ti & 1, nxt = cur ^ 1;

        CP_WAIT0();
        __syncthreads();

        if (ti + 1 < NT) {
            const __half* Kg1  = Kg + (size_t)(ti + 1) * 64 * DIM;
            const __half* Vtg1 = Vtg + (size_t)(ti + 1) * 64;
#pragma unroll
            for (int it = 0; it < 4; it++) {
                const int c = tid + it * 128;
                const int row = c >> 3, ch = c & 7;
                CP_ASYNC16(kb_u32[nxt] + row * PU * 4 + ch * 16,
                           (const char*)(Kg1 + (size_t)row * DIM) + ch * 16);
            }
#pragma unroll
            for (int it = 0; it < 4; it++) {
                const int c = tid + it * 128;
                const int row = c >> 3, ch = c & 7;
                CP_ASYNC16(vb_u32[nxt] + row * PU * 4 + ch * 16,
                           (const char*)(Vtg1 + (size_t)row * SEQ) + ch * 16);
            }
            CP_COMMIT();
        }

        const uint32_t* K_s = Kb[cur];
        const uint32_t* V_s = Vb[cur];

        // ---- S = Q @ K^T ----
        float sacc[8][4];
#pragma unroll
        for (int j = 0; j < 8; j++)
#pragma unroll
            for (int c = 0; c < 4; c++) sacc[j][c] = 0.f;

#pragma unroll
        for (int ks = 0; ks < 4; ks++) {
#pragma unroll
            for (int j = 0; j < 8; j++) {
                uint32_t bf[2];
                bf[0] = K_s[(j * 8 + g) * PU + ks * 8 + t];
                bf[1] = K_s[(j * 8 + g) * PU + ks * 8 + t + 4];
                mma_f16(sacc[j], qf[ks], bf);
            }
        }

        // ---- online softmax ----
        float mx_lo = -INFINITY, mx_hi = -INFINITY;
#pragma unroll
        for (int j = 0; j < 8; j++) {
            mx_lo = fmaxf(mx_lo, fmaxf(sacc[j][0], sacc[j][1]));
            mx_hi = fmaxf(mx_hi, fmaxf(sacc[j][2], sacc[j][3]));
        }
        mx_lo = fmaxf(mx_lo, __shfl_xor_sync(0xffffffffu, mx_lo, 1));
        mx_lo = fmaxf(mx_lo, __shfl_xor_sync(0xffffffffu, mx_lo, 2));
        mx_hi = fmaxf(mx_hi, __shfl_xor_sync(0xffffffffu, mx_hi, 1));
        mx_hi = fmaxf(mx_hi, __shfl_xor_sync(0xffffffffu, mx_hi, 2));

        const float mnew_lo = fmaxf(m_lo, mx_lo);
        const float mnew_hi = fmaxf(m_hi, mx_hi);
        const float corr_lo = __expf(m_lo - mnew_lo);
        const float corr_hi = __expf(m_hi - mnew_hi);
        m_lo = mnew_lo; m_hi = mnew_hi;

        uint32_t ph_lo[8], ph_hi[8];
        float sum_lo = 0.f, sum_hi = 0.f;
#pragma unroll
        for (int j = 0; j < 8; j++) {
            const float p0 = __expf(sacc[j][0] - mnew_lo);
            const float p1 = __expf(sacc[j][1] - mnew_lo);
            const float p2 = __expf(sacc[j][2] - mnew_hi);
            const float p3 = __expf(sacc[j][3] - mnew_hi);
            sum_lo += p0 + p1;
            sum_hi += p2 + p3;
            ph_lo[j] = h2_as_u32(__floats2half2_rn(p0, p1));
            ph_hi[j] = h2_as_u32(__floats2half2_rn(p2, p3));
        }
        sum_lo += __shfl_xor_sync(0xffffffffu, sum_lo, 1);
        sum_lo += __shfl_xor_sync(0xffffffffu, sum_lo, 2);
        sum_hi += __shfl_xor_sync(0xffffffffu, sum_hi, 1);
        sum_hi += __shfl_xor_sync(0xffffffffu, sum_hi, 2);
        l_lo = l_lo * corr_lo + sum_lo;
        l_hi = l_hi * corr_hi + sum_hi;

#pragma unroll
        for (int j = 0; j < 8; j++) {
            oacc[j][0] *= corr_lo; oacc[j][1] *= corr_lo;
            oacc[j][2] *= corr_hi; oacc[j][3] *= corr_hi;
        }

        // ---- O += P @ V ----
#pragma unroll
        for (int ks = 0; ks < 4; ks++) {
            uint32_t af[4];
            af[0] = ph_lo[2 * ks];
            af[1] = ph_hi[2 * ks];
            af[2] = ph_lo[2 * ks + 1];
            af[3] = ph_hi[2 * ks + 1];
#pragma unroll
            for (int j = 0; j < 8; j++) {
                uint32_t bf[2];
                bf[0] = V_s[(j * 8 + g) * PU + ks * 8 + t];
                bf[1] = V_s[(j * 8 + g) * PU + ks * 8 + t + 4];
                mma_f16(oacc[j], af, bf);
            }
        }
    }

    // ---- epilogue (fp16 out) ----
    __half* Og = O + (size_t)b * SEQ * DIM + h * DHEAD;
    const float inv_lo = 1.f / l_lo;
    const float inv_hi = 1.f / l_hi;
    const int r_lo = q0 + wrow + g;
    const int r_hi = r_lo + 8;
#pragma unroll
    for (int j = 0; j < 8; j++) {
        const int c = j * 8 + 2 * t;
        *(__half2*)(Og + (size_t)r_lo * DIM + c) =
            __floats2half2_rn(oacc[j][0] * inv_lo, oacc[j][1] * inv_lo);
        *(__half2*)(Og + (size_t)r_hi * DIM + c) =
            __floats2half2_rn(oacc[j][2] * inv_hi, oacc[j][3] * inv_hi);
    }
}

// ============================================================================
// kernel_launch
// ============================================================================
extern "C" void kernel_launch(void* const* d_in, const int* in_sizes, int n_in,
                              void* d_out, int out_size)
{
    const float* x   = (const float*)d_in[0];
    const float* Wq  = (const float*)d_in[1];
    const float* Wk  = (const float*)d_in[2];
    const float* Wv  = (const float*)d_in[3];
    const float* Wff = (const float*)d_in[4];
    const float* bff = (const float*)d_in[5];
    float* out = (float*)d_out;

    __half *xh, *wq, *wk, *wv, *wf, *qh, *kh, *vh, *vt, *attn;
    cudaGetSymbolAddress((void**)&xh,   g_xh);
    cudaGetSymbolAddress((void**)&wq,   g_wq);
    cudaGetSymbolAddress((void**)&wk,   g_wk);
    cudaGetSymbolAddress((void**)&wv,   g_wv);
    cudaGetSymbolAddress((void**)&wf,   g_wf);
    cudaGetSymbolAddress((void**)&qh,   g_qh);
    cudaGetSymbolAddress((void**)&kh,   g_kh);
    cudaGetSymbolAddress((void**)&vh,   g_vh);
    cudaGetSymbolAddress((void**)&vt,   g_vt);
    cudaGetSymbolAddress((void**)&attn, g_attn);

    cudaFuncSetAttribute(flash_attn_f16,
                         cudaFuncAttributeMaxDynamicSharedMemorySize, FA_SMEM);

    // ---- converts ----
    const int nx = MROWS * DIM;       // 4M
    const int nw = DIM * DIM;         // 1M
    f32_to_f16<<<nx / 1024, 256>>>(x,   xh, nx);
    f32_to_f16<<<nw / 1024, 256>>>(Wq,  wq, nw);
    f32_to_f16<<<nw / 1024, 256>>>(Wk,  wk, nw);
    f32_to_f16<<<nw / 1024, 256>>>(Wv,  wv, nw);
    f32_to_f16<<<nw / 1024, 256>>>(Wff, wf, nw);

    dim3 gemm_grid(DIM / HBN, MROWS / HBM);   // (8, 32)
    const float qscale = 1.0f / 32.0f;        // 1/sqrt(1024)

    gemm_f16<<<gemm_grid, 256>>>(xh, wq, qh, MROWS, DIM, DIM, qscale, nullptr, 1);
    gemm_f16<<<gemm_grid, 256>>>(xh, wk, kh, MROWS, DIM, DIM, 1.0f, nullptr, 1);
    gemm_f16<<<gemm_grid, 256>>>(xh, wv, vh, MROWS, DIM, DIM, 1.0f, nullptr, 1);

    dim3 tr_grid(SEQ / 64, HEADS, BATCH);
    transpose_v<<<tr_grid, 128>>>(vh, vt);

    dim3 att_grid(SEQ / 64, HEADS, BATCH);    // (32, 16, 2)
    flash_attn_f16<<<att_grid, 128, FA_SMEM>>>(qh, kh, vt, attn);

    gemm_f16<<<gemm_grid, 256>>>(attn, wf, out, MROWS, DIM, DIM, 1.0f, bff, 0);
}